// round 1
// baseline (speedup 1.0000x reference)
#include <cuda_runtime.h>
#include <math.h>

// Problem constants
#define BB 2
#define CC 512
#define NN 4096          // d*h*w = 16*16*16
#define NGROUPS 32
#define CPG 16           // channels per group
#define EPS 1e-6f

// Scratch (device globals: allocation-free per harness rules)
__device__ float g_h[(size_t)BB * CC * NN];     // groupnorm output
__device__ float g_q[(size_t)BB * CC * NN];
__device__ float g_k[(size_t)BB * CC * NN];
__device__ float g_v[(size_t)BB * CC * NN];
__device__ float g_o[(size_t)BB * CC * NN];
__device__ float g_s[(size_t)BB * NN * NN];     // attention logits/probs (128 MiB)

__device__ __forceinline__ float* getbuf(int s) {
    switch (s) {
        case 0: return g_h;
        case 1: return g_q;
        case 2: return g_k;
        case 3: return g_v;
        case 4: return g_o;
    }
    return nullptr;
}

// ---------------------------------------------------------------------------
// GroupNorm: one block per (batch, group). Group = 16 channels x 4096 = 65536.
// ---------------------------------------------------------------------------
__global__ void gn_kernel(const float* __restrict__ x,
                          const float* __restrict__ gamma,
                          const float* __restrict__ beta) {
    const int bg = blockIdx.x;
    const int b = bg >> 5;
    const int g = bg & 31;
    const size_t base = ((size_t)b * CC + (size_t)g * CPG) * NN;
    const float* xp = x + base;
    float* hp = g_h + base;
    const int CNT = CPG * NN;  // 65536

    float s = 0.f, ss = 0.f;
    for (int i = threadIdx.x * 4; i < CNT; i += blockDim.x * 4) {
        float4 v = *reinterpret_cast<const float4*>(xp + i);
        s += v.x + v.y + v.z + v.w;
        ss += v.x * v.x + v.y * v.y + v.z * v.z + v.w * v.w;
    }
    // warp reduce
    #pragma unroll
    for (int o = 16; o; o >>= 1) {
        s += __shfl_xor_sync(0xffffffffu, s, o);
        ss += __shfl_xor_sync(0xffffffffu, ss, o);
    }
    __shared__ float sh_s[16], sh_ss[16];
    const int w = threadIdx.x >> 5, l = threadIdx.x & 31;
    const int nw = blockDim.x >> 5;
    if (l == 0) { sh_s[w] = s; sh_ss[w] = ss; }
    __syncthreads();
    if (threadIdx.x == 0) {
        float S = 0.f, SS = 0.f;
        for (int i = 0; i < nw; i++) { S += sh_s[i]; SS += sh_ss[i]; }
        float mean = S / (float)CNT;
        float var = SS / (float)CNT - mean * mean;
        sh_s[0] = mean;
        sh_ss[0] = rsqrtf(var + EPS);
    }
    __syncthreads();
    const float mean = sh_s[0], rstd = sh_ss[0];
    for (int i = threadIdx.x * 4; i < CNT; i += blockDim.x * 4) {
        const int ch = g * CPG + (i >> 12);   // all 4 elems same channel (NN=4096)
        const float ga = gamma[ch], be = beta[ch];
        float4 v = *reinterpret_cast<const float4*>(xp + i);
        float4 o;
        o.x = (v.x - mean) * rstd * ga + be;
        o.y = (v.y - mean) * rstd * ga + be;
        o.z = (v.z - mean) * rstd * ga + be;
        o.w = (v.w - mean) * rstd * ga + be;
        *reinterpret_cast<float4*>(hp + i) = o;
    }
}

// ---------------------------------------------------------------------------
// GEMM NN: C[b][M=512][NN] = W[M,K] * Bbuf[b][K][NN] + bias (+ residual)
// 128x128x8 tile, 256 threads, 8x8 per thread.
// ---------------------------------------------------------------------------
__global__ void __launch_bounds__(256, 2)
gemm_nn(const float* __restrict__ W, const float* __restrict__ bias,
        const float* __restrict__ resid, float* __restrict__ Cext,
        int bsel, int csel, int K) {
    const int bz = blockIdx.z;
    const float* Bp = getbuf(bsel) + (size_t)bz * K * NN;
    float* Cp = (csel >= 0 ? getbuf(csel) : Cext) + (size_t)bz * CC * NN;
    const float* Rp = resid ? resid + (size_t)bz * CC * NN : nullptr;

    __shared__ float As[8][128];
    __shared__ float Bs[8][128];
    const int tid = threadIdx.x;
    const int m0 = blockIdx.y * 128, n0 = blockIdx.x * 128;
    const int tm = (tid >> 4) << 3, tn = (tid & 15) << 3;
    // A load: W row-major [M,K], k-contiguous -> transpose into As
    const int arow = tid >> 1, acol = (tid & 1) << 2;
    // B load: [K, NN], n-contiguous -> direct
    const int brow = tid >> 5, bcol = (tid & 31) << 2;

    float acc[8][8] = {};
    for (int k0 = 0; k0 < K; k0 += 8) {
        float4 av = *reinterpret_cast<const float4*>(W + (size_t)(m0 + arow) * K + k0 + acol);
        As[acol + 0][arow] = av.x; As[acol + 1][arow] = av.y;
        As[acol + 2][arow] = av.z; As[acol + 3][arow] = av.w;
        *reinterpret_cast<float4*>(&Bs[brow][bcol]) =
            *reinterpret_cast<const float4*>(Bp + (size_t)(k0 + brow) * NN + n0 + bcol);
        __syncthreads();
        #pragma unroll
        for (int kk = 0; kk < 8; kk++) {
            float ra[8], rb[8];
            #pragma unroll
            for (int i = 0; i < 8; i++) ra[i] = As[kk][tm + i];
            #pragma unroll
            for (int j = 0; j < 8; j++) rb[j] = Bs[kk][tn + j];
            #pragma unroll
            for (int i = 0; i < 8; i++)
                #pragma unroll
                for (int j = 0; j < 8; j++) acc[i][j] += ra[i] * rb[j];
        }
        __syncthreads();
    }
    #pragma unroll
    for (int i = 0; i < 8; i++) {
        const float bi = bias[m0 + tm + i];
        #pragma unroll
        for (int j = 0; j < 8; j++) {
            const size_t idx = (size_t)(m0 + tm + i) * NN + n0 + tn + j;
            float v = acc[i][j] + bi;
            if (Rp) v += Rp[idx];
            Cp[idx] = v;
        }
    }
}

// ---------------------------------------------------------------------------
// S = scale * Q^T K : S[b][i][j] = scale * sum_c q[b][c][i] k[b][c][j]
// Both operand tiles are n-contiguous (TN form is the friendly one here).
// ---------------------------------------------------------------------------
__global__ void __launch_bounds__(256, 2)
gemm_s_kernel() {
    const int bz = blockIdx.z;
    const float* Qp = g_q + (size_t)bz * CC * NN;
    const float* Kp = g_k + (size_t)bz * CC * NN;
    float* Sp = g_s + (size_t)bz * NN * NN;

    __shared__ float As[8][128];
    __shared__ float Bs[8][128];
    const int tid = threadIdx.x;
    const int m0 = blockIdx.y * 128, n0 = blockIdx.x * 128;
    const int tm = (tid >> 4) << 3, tn = (tid & 15) << 3;
    const int lrow = tid >> 5, lcol = (tid & 31) << 2;

    float acc[8][8] = {};
    for (int k0 = 0; k0 < CC; k0 += 8) {
        *reinterpret_cast<float4*>(&As[lrow][lcol]) =
            *reinterpret_cast<const float4*>(Qp + (size_t)(k0 + lrow) * NN + m0 + lcol);
        *reinterpret_cast<float4*>(&Bs[lrow][lcol]) =
            *reinterpret_cast<const float4*>(Kp + (size_t)(k0 + lrow) * NN + n0 + lcol);
        __syncthreads();
        #pragma unroll
        for (int kk = 0; kk < 8; kk++) {
            float ra[8], rb[8];
            #pragma unroll
            for (int i = 0; i < 8; i++) ra[i] = As[kk][tm + i];
            #pragma unroll
            for (int j = 0; j < 8; j++) rb[j] = Bs[kk][tn + j];
            #pragma unroll
            for (int i = 0; i < 8; i++)
                #pragma unroll
                for (int j = 0; j < 8; j++) acc[i][j] += ra[i] * rb[j];
        }
        __syncthreads();
    }
    const float scale = 0.044194173824159216f;   // 512^-0.5
    #pragma unroll
    for (int i = 0; i < 8; i++)
        #pragma unroll
        for (int j = 0; j < 8; j++)
            Sp[(size_t)(m0 + tm + i) * NN + n0 + tn + j] = acc[i][j] * scale;
}

// ---------------------------------------------------------------------------
// Row softmax over g_s: 8192 rows of 4096.
// ---------------------------------------------------------------------------
__global__ void softmax_kernel() {
    float* p = g_s + (size_t)blockIdx.x * NN;
    const int tid = threadIdx.x;

    float mx = -INFINITY;
    for (int i = tid * 4; i < NN; i += blockDim.x * 4) {
        float4 v = *reinterpret_cast<const float4*>(p + i);
        mx = fmaxf(mx, fmaxf(fmaxf(v.x, v.y), fmaxf(v.z, v.w)));
    }
    #pragma unroll
    for (int o = 16; o; o >>= 1) mx = fmaxf(mx, __shfl_xor_sync(0xffffffffu, mx, o));
    __shared__ float sh[8];
    const int w = tid >> 5, l = tid & 31;
    if (l == 0) sh[w] = mx;
    __syncthreads();
    if (tid == 0) {
        float m = sh[0];
        for (int i = 1; i < (int)(blockDim.x >> 5); i++) m = fmaxf(m, sh[i]);
        sh[0] = m;
    }
    __syncthreads();
    mx = sh[0];
    __syncthreads();

    float s = 0.f;
    for (int i = tid * 4; i < NN; i += blockDim.x * 4) {
        float4 v = *reinterpret_cast<const float4*>(p + i);
        v.x = __expf(v.x - mx); v.y = __expf(v.y - mx);
        v.z = __expf(v.z - mx); v.w = __expf(v.w - mx);
        *reinterpret_cast<float4*>(p + i) = v;
        s += v.x + v.y + v.z + v.w;
    }
    #pragma unroll
    for (int o = 16; o; o >>= 1) s += __shfl_xor_sync(0xffffffffu, s, o);
    if (l == 0) sh[w] = s;
    __syncthreads();
    if (tid == 0) {
        float S = 0.f;
        for (int i = 0; i < (int)(blockDim.x >> 5); i++) S += sh[i];
        sh[0] = 1.0f / S;
    }
    __syncthreads();
    const float inv = sh[0];
    for (int i = tid * 4; i < NN; i += blockDim.x * 4) {
        float4 v = *reinterpret_cast<const float4*>(p + i);
        v.x *= inv; v.y *= inv; v.z *= inv; v.w *= inv;
        *reinterpret_cast<float4*>(p + i) = v;
    }
}

// ---------------------------------------------------------------------------
// O = V * S^T : O[b][c][i] = sum_j v[b][c][j] * s[b][i][j]   (NT form)
// ---------------------------------------------------------------------------
__global__ void __launch_bounds__(256, 2)
gemm_o_kernel() {
    const int bz = blockIdx.z;
    const float* Vp = g_v + (size_t)bz * CC * NN;
    const float* Sp = g_s + (size_t)bz * NN * NN;
    float* Op = g_o + (size_t)bz * CC * NN;

    __shared__ float As[8][128];
    __shared__ float Bs[8][128];
    const int tid = threadIdx.x;
    const int m0 = blockIdx.y * 128, n0 = blockIdx.x * 128;
    const int tm = (tid >> 4) << 3, tn = (tid & 15) << 3;
    const int arow = tid >> 1, acol = (tid & 1) << 2;

    float acc[8][8] = {};
    for (int k0 = 0; k0 < NN; k0 += 8) {
        float4 av = *reinterpret_cast<const float4*>(Vp + (size_t)(m0 + arow) * NN + k0 + acol);
        As[acol + 0][arow] = av.x; As[acol + 1][arow] = av.y;
        As[acol + 2][arow] = av.z; As[acol + 3][arow] = av.w;
        float4 bv = *reinterpret_cast<const float4*>(Sp + (size_t)(n0 + arow) * NN + k0 + acol);
        Bs[acol + 0][arow] = bv.x; Bs[acol + 1][arow] = bv.y;
        Bs[acol + 2][arow] = bv.z; Bs[acol + 3][arow] = bv.w;
        __syncthreads();
        #pragma unroll
        for (int kk = 0; kk < 8; kk++) {
            float ra[8], rb[8];
            #pragma unroll
            for (int i = 0; i < 8; i++) ra[i] = As[kk][tm + i];
            #pragma unroll
            for (int j = 0; j < 8; j++) rb[j] = Bs[kk][tn + j];
            #pragma unroll
            for (int i = 0; i < 8; i++)
                #pragma unroll
                for (int j = 0; j < 8; j++) acc[i][j] += ra[i] * rb[j];
        }
        __syncthreads();
    }
    #pragma unroll
    for (int i = 0; i < 8; i++)
        #pragma unroll
        for (int j = 0; j < 8; j++)
            Op[(size_t)(m0 + tm + i) * NN + n0 + tn + j] = acc[i][j];
}

// ---------------------------------------------------------------------------
extern "C" void kernel_launch(void* const* d_in, const int* in_sizes, int n_in,
                              void* d_out, int out_size) {
    const float* x     = (const float*)d_in[0];
    const float* gamma = (const float*)d_in[1];
    const float* beta  = (const float*)d_in[2];
    const float* wq    = (const float*)d_in[3];
    const float* bq    = (const float*)d_in[4];
    const float* wk    = (const float*)d_in[5];
    const float* bk    = (const float*)d_in[6];
    const float* wv    = (const float*)d_in[7];
    const float* bv    = (const float*)d_in[8];
    const float* wo    = (const float*)d_in[9];
    const float* bo    = (const float*)d_in[10];
    float* out = (float*)d_out;

    // 1) GroupNorm -> g_h
    gn_kernel<<<BB * NGROUPS, 256>>>(x, gamma, beta);

    // 2) Q, K, V projections: 512x4096 = W(512x512) * h
    dim3 gproj(NN / 128, CC / 128, BB);
    gemm_nn<<<gproj, 256>>>(wq, bq, nullptr, nullptr, /*bsel=*/0, /*csel=*/1, CC);
    gemm_nn<<<gproj, 256>>>(wk, bk, nullptr, nullptr, 0, 2, CC);
    gemm_nn<<<gproj, 256>>>(wv, bv, nullptr, nullptr, 0, 3, CC);

    // 3) S = scale * Q^T K
    dim3 gs(NN / 128, NN / 128, BB);
    gemm_s_kernel<<<gs, 256>>>();

    // 4) softmax rows
    softmax_kernel<<<BB * NN, 256>>>();

    // 5) O = V * S^T
    gemm_o_kernel<<<gproj, 256>>>();

    // 6) out = x + wo * O + bo
    gemm_nn<<<gproj, 256>>>(wo, bo, x, out, /*bsel=*/4, /*csel=*/-1, CC);
}

// round 4
// speedup vs baseline: 3.0550x; 3.0550x over previous
#include <cuda_runtime.h>
#include <cuda_bf16.h>
#include <cstdint>
#include <math.h>

#define BB 2
#define CC 512
#define NN 4096
#define NGROUPS 32
#define CPG 16
#define EPS 1e-6f

typedef __nv_bfloat16 bf16;
typedef __nv_bfloat162 bf162;

// ---------------- scratch globals ----------------
__device__ bf16 g_ht_hi[(size_t)BB * NN * CC], g_ht_lo[(size_t)BB * NN * CC];   // h^T [b][n][c]
__device__ bf16 g_qt_hi[(size_t)BB * NN * CC], g_qt_lo[(size_t)BB * NN * CC];   // q^T [b][n][c]
__device__ bf16 g_kt_hi[(size_t)BB * NN * CC], g_kt_lo[(size_t)BB * NN * CC];
__device__ bf16 g_v_hi [(size_t)BB * CC * NN], g_v_lo [(size_t)BB * CC * NN];   // v [b][c][n]
__device__ bf16 g_ot_hi[(size_t)BB * NN * CC], g_ot_lo[(size_t)BB * NN * CC];   // o^T [b][n][c]
__device__ bf16 g_wq_hi[CC * CC], g_wq_lo[CC * CC];
__device__ bf16 g_wk_hi[CC * CC], g_wk_lo[CC * CC];
__device__ bf16 g_wv_hi[CC * CC], g_wv_lo[CC * CC];
__device__ bf16 g_wo_hi[CC * CC], g_wo_lo[CC * CC];
__device__ float g_s[(size_t)BB * NN * NN];                                      // logits
__device__ bf16 g_p_hi[(size_t)BB * NN * NN], g_p_lo[(size_t)BB * NN * NN];     // probs

// ---------------- PTX helpers (plain sm_80-era: mma.sync / ldmatrix / cp.async) --
__device__ __forceinline__ uint32_t smem_u32(const void* p) {
    uint32_t a;
    asm("{ .reg .u64 t; cvta.to.shared.u64 t, %1; cvt.u32.u64 %0, t; }" : "=r"(a) : "l"(p));
    return a;
}
__device__ __forceinline__ void cp16(uint32_t saddr, const void* g) {
    asm volatile("cp.async.cg.shared.global [%0], [%1], 16;" :: "r"(saddr), "l"(g) : "memory");
}
#define CP_COMMIT() asm volatile("cp.async.commit_group;" ::: "memory")
#define CP_WAIT(n)  asm volatile("cp.async.wait_group %0;" :: "n"(n) : "memory")

__device__ __forceinline__ void ldm_x4(uint32_t* r, uint32_t addr) {
    asm volatile("ldmatrix.sync.aligned.m8n8.x4.shared.b16 {%0,%1,%2,%3}, [%4];"
        : "=r"(r[0]), "=r"(r[1]), "=r"(r[2]), "=r"(r[3]) : "r"(addr));
}
__device__ __forceinline__ void mma_bf16(float* d, const uint32_t* a, const uint32_t* b) {
    asm volatile("mma.sync.aligned.m16n8k16.row.col.f32.bf16.bf16.f32 "
        "{%0,%1,%2,%3}, {%4,%5,%6,%7}, {%8,%9}, {%0,%1,%2,%3};"
        : "+f"(d[0]), "+f"(d[1]), "+f"(d[2]), "+f"(d[3])
        : "r"(a[0]), "r"(a[1]), "r"(a[2]), "r"(a[3]), "r"(b[0]), "r"(b[1]));
}
#define SWZ(o) ((o) ^ (((o) >> 3) & 0x70))

// ---------------- GroupNorm -> h^T hi/lo ----------------
__global__ void gn_kernel(const float* __restrict__ x,
                          const float* __restrict__ gamma,
                          const float* __restrict__ beta) {
    __shared__ float tile[16][257];
    __shared__ float red[8], red2[8];
    __shared__ float sga[16], sbe[16], s_mean, s_rstd;
    const int bg = blockIdx.x, b = bg >> 5, g = bg & 31;
    const size_t xbase = ((size_t)b * CC + (size_t)g * CPG) * NN;
    const float* xp = x + xbase;
    const int tid = threadIdx.x;
    if (tid < 16) { sga[tid] = gamma[g * CPG + tid]; sbe[tid] = beta[g * CPG + tid]; }

    float s = 0.f, ss = 0.f;
    for (int i = tid * 4; i < CPG * NN; i += 1024) {
        float4 v = *reinterpret_cast<const float4*>(xp + i);
        s += v.x + v.y + v.z + v.w;
        ss += v.x * v.x + v.y * v.y + v.z * v.z + v.w * v.w;
    }
    #pragma unroll
    for (int o = 16; o; o >>= 1) {
        s += __shfl_xor_sync(0xffffffffu, s, o);
        ss += __shfl_xor_sync(0xffffffffu, ss, o);
    }
    if ((tid & 31) == 0) { red[tid >> 5] = s; red2[tid >> 5] = ss; }
    __syncthreads();
    if (tid == 0) {
        float S = 0.f, SS = 0.f;
        for (int i = 0; i < 8; i++) { S += red[i]; SS += red2[i]; }
        float mean = S / (float)(CPG * NN);
        s_mean = mean;
        s_rstd = rsqrtf(SS / (float)(CPG * NN) - mean * mean + EPS);
    }
    __syncthreads();
    const float mean = s_mean, rstd = s_rstd;

    for (int n0 = 0; n0 < NN; n0 += 256) {
        __syncthreads();
        for (int i = tid; i < 16 * 256; i += 256) {
            int c = i >> 8, n = i & 255;
            tile[c][n] = xp[(size_t)c * NN + n0 + n];
        }
        __syncthreads();
        const int n = n0 + tid;
        __align__(16) bf162 hv[8], lv[8];
        #pragma unroll
        for (int c2 = 0; c2 < 8; c2++) {
            float v0 = (tile[2 * c2][tid] - mean) * rstd * sga[2 * c2] + sbe[2 * c2];
            float v1 = (tile[2 * c2 + 1][tid] - mean) * rstd * sga[2 * c2 + 1] + sbe[2 * c2 + 1];
            bf16 h0 = __float2bfloat16(v0), h1 = __float2bfloat16(v1);
            hv[c2] = __halves2bfloat162(h0, h1);
            lv[c2] = __halves2bfloat162(__float2bfloat16(v0 - __bfloat162float(h0)),
                                        __float2bfloat16(v1 - __bfloat162float(h1)));
        }
        const size_t dst = ((size_t)b * NN + n) * CC + (size_t)g * CPG;
        *reinterpret_cast<uint4*>(g_ht_hi + dst)     = reinterpret_cast<uint4*>(hv)[0];
        *reinterpret_cast<uint4*>(g_ht_hi + dst + 8) = reinterpret_cast<uint4*>(hv)[1];
        *reinterpret_cast<uint4*>(g_ht_lo + dst)     = reinterpret_cast<uint4*>(lv)[0];
        *reinterpret_cast<uint4*>(g_ht_lo + dst + 8) = reinterpret_cast<uint4*>(lv)[1];
    }
}

// ---------------- weight hi/lo decomposition ----------------
__global__ void decomp_kernel(const float* __restrict__ src, bf16* __restrict__ hi,
                              bf16* __restrict__ lo, int n4) {
    int i = blockIdx.x * blockDim.x + threadIdx.x;
    if (i >= n4) return;
    float4 v = reinterpret_cast<const float4*>(src)[i];
    bf16 h0 = __float2bfloat16(v.x), h1 = __float2bfloat16(v.y);
    bf16 h2 = __float2bfloat16(v.z), h3 = __float2bfloat16(v.w);
    __align__(8) bf162 hv[2] = { __halves2bfloat162(h0, h1), __halves2bfloat162(h2, h3) };
    __align__(8) bf162 lv[2] = {
        __halves2bfloat162(__float2bfloat16(v.x - __bfloat162float(h0)),
                           __float2bfloat16(v.y - __bfloat162float(h1))),
        __halves2bfloat162(__float2bfloat16(v.z - __bfloat162float(h2)),
                           __float2bfloat16(v.w - __bfloat162float(h3))) };
    *reinterpret_cast<uint2*>(hi + 4 * (size_t)i) = *reinterpret_cast<uint2*>(hv);
    *reinterpret_cast<uint2*>(lo + 4 * (size_t)i) = *reinterpret_cast<uint2*>(lv);
}

// ---------------- softmax: fp32 logits -> bf16 hi/lo probs ----------------
__global__ void softmax_kernel() {
    __shared__ float row[NN];
    __shared__ float red[8];
    __shared__ float s_bcast;
    const size_t rbase = (size_t)blockIdx.x * NN;
    const float* sp = g_s + rbase;
    const int tid = threadIdx.x;

    float mx = -1e30f;
    for (int i = tid * 4; i < NN; i += 1024) {
        float4 v = *reinterpret_cast<const float4*>(sp + i);
        *reinterpret_cast<float4*>(row + i) = v;
        mx = fmaxf(fmaxf(v.x, v.y), fmaxf(fmaxf(v.z, v.w), mx));
    }
    #pragma unroll
    for (int o = 16; o; o >>= 1) mx = fmaxf(mx, __shfl_xor_sync(0xffffffffu, mx, o));
    if ((tid & 31) == 0) red[tid >> 5] = mx;
    __syncthreads();
    if (tid == 0) {
        float m = red[0];
        for (int i = 1; i < 8; i++) m = fmaxf(m, red[i]);
        s_bcast = m;
    }
    __syncthreads();
    mx = s_bcast;
    __syncthreads();

    float s = 0.f;
    for (int i = tid * 4; i < NN; i += 1024) {
        float4 v = *reinterpret_cast<float4*>(row + i);
        v.x = __expf(v.x - mx); v.y = __expf(v.y - mx);
        v.z = __expf(v.z - mx); v.w = __expf(v.w - mx);
        *reinterpret_cast<float4*>(row + i) = v;
        s += v.x + v.y + v.z + v.w;
    }
    #pragma unroll
    for (int o = 16; o; o >>= 1) s += __shfl_xor_sync(0xffffffffu, s, o);
    if ((tid & 31) == 0) red[tid >> 5] = s;
    __syncthreads();
    if (tid == 0) {
        float S = 0.f;
        for (int i = 0; i < 8; i++) S += red[i];
        s_bcast = 1.0f / S;
    }
    __syncthreads();
    const float inv = s_bcast;

    for (int i = tid * 4; i < NN; i += 1024) {
        float4 v = *reinterpret_cast<float4*>(row + i);
        float p0 = v.x * inv, p1 = v.y * inv, p2 = v.z * inv, p3 = v.w * inv;
        bf16 h0 = __float2bfloat16(p0), h1 = __float2bfloat16(p1);
        bf16 h2 = __float2bfloat16(p2), h3 = __float2bfloat16(p3);
        __align__(8) bf162 hv[2] = { __halves2bfloat162(h0, h1), __halves2bfloat162(h2, h3) };
        __align__(8) bf162 lv[2] = {
            __halves2bfloat162(__float2bfloat16(p0 - __bfloat162float(h0)),
                               __float2bfloat16(p1 - __bfloat162float(h1))),
            __halves2bfloat162(__float2bfloat16(p2 - __bfloat162float(h2)),
                               __float2bfloat16(p3 - __bfloat162float(h3))) };
        *reinterpret_cast<uint2*>(g_p_hi + rbase + i) = *reinterpret_cast<uint2*>(hv);
        *reinterpret_cast<uint2*>(g_p_lo + rbase + i) = *reinterpret_cast<uint2*>(lv);
    }
}

// ---------------- HMMA bf16x3 GEMM ----------------
// D[M,N] = scale * (Ahi+Alo)[M,K] . (Bhi+Blo)[N,K]^T  (+bias)(+resid)
// Block 128x128, BK=64, 8 warps of 64(M)x32(N), double-buffered cp.async.
#define TILE_B 16384                      // one 128x64 bf16 tile (128B rows, SW128)
#define STAGE_B (4 * TILE_B)              // Ahi, Alo, Bhi, Blo
#define SMEM_TOTAL (2 * STAGE_B)          // 131072

__device__ __forceinline__ void load_tile_async(const bf16* __restrict__ src, int row0,
                                                int ld, int k0, uint32_t sdst, int tid) {
    #pragma unroll
    for (int i = 0; i < 4; i++) {
        int c = tid + i * 256;                  // 0..1023 16B chunks
        int r = c >> 3, ck = c & 7;
        cp16(sdst + SWZ((uint32_t)(r * 128 + ck * 16)),
             src + (size_t)(row0 + r) * ld + k0 + ck * 8);
    }
}

__global__ void __launch_bounds__(256, 1)
mma_gemm(const bf16* __restrict__ Ah, const bf16* __restrict__ Al,
         const bf16* __restrict__ Bh, const bf16* __restrict__ Bl,
         int lda, int ldb, int K, size_t sA, size_t sB,
         float* __restrict__ Cf, bf16* __restrict__ Chi, bf16* __restrict__ Clo,
         int ldc, size_t sC,
         const float* __restrict__ bias, int bias_mode,   // 0 none, 1 per-M, 2 per-N
         const float* __restrict__ resid, size_t sR, float scale) {
    extern __shared__ __align__(1024) char smem[];
    const uint32_t sb = smem_u32(smem);
    const int tid = threadIdx.x, wid = tid >> 5, lane = tid & 31;
    const int bz = blockIdx.z;
    const int m0 = blockIdx.y * 128, n0 = blockIdx.x * 128;
    const int wm0 = (wid & 1) * 64, wn0 = (wid >> 1) * 32;

    const bf16* pAh = Ah + (size_t)bz * sA;
    const bf16* pAl = Al + (size_t)bz * sA;
    const bf16* pBh = Bh + (size_t)bz * sB;
    const bf16* pBl = Bl + (size_t)bz * sB;

    const int NC = K >> 6;
    float acc[4][4][4] = {};

    // prologue: stage 0
    {
        uint32_t base = sb;
        load_tile_async(pAh, m0, lda, 0, base, tid);
        load_tile_async(pAl, m0, lda, 0, base + TILE_B, tid);
        load_tile_async(pBh, n0, ldb, 0, base + 2 * TILE_B, tid);
        load_tile_async(pBl, n0, ldb, 0, base + 3 * TILE_B, tid);
        CP_COMMIT();
    }

    for (int c = 0; c < NC; c++) {
        if (c + 1 < NC) {
            uint32_t base = sb + ((c + 1) & 1) * STAGE_B;
            const int k0 = (c + 1) << 6;
            load_tile_async(pAh, m0, lda, k0, base, tid);
            load_tile_async(pAl, m0, lda, k0, base + TILE_B, tid);
            load_tile_async(pBh, n0, ldb, k0, base + 2 * TILE_B, tid);
            load_tile_async(pBl, n0, ldb, k0, base + 3 * TILE_B, tid);
            CP_COMMIT();
            CP_WAIT(1);
        } else {
            CP_WAIT(0);
        }
        __syncthreads();

        const uint32_t base = sb + (c & 1) * STAGE_B;
        #pragma unroll
        for (int ks = 0; ks < 4; ks++) {
            // B fragments: 2x ldmatrix.x4 covering 4 n8-tiles, hi and lo
            uint32_t bhi[2][4], blo[2][4];
            #pragma unroll
            for (int nt2 = 0; nt2 < 2; nt2++) {
                const uint32_t off = SWZ((uint32_t)(
                    (wn0 + nt2 * 16 + ((lane >> 4) & 1) * 8 + (lane & 7)) * 128 +
                    ks * 32 + ((lane >> 3) & 1) * 16));
                ldm_x4(bhi[nt2], base + 2 * TILE_B + off);
                ldm_x4(blo[nt2], base + 3 * TILE_B + off);
            }
            #pragma unroll
            for (int mt = 0; mt < 4; mt++) {
                uint32_t ahi[4], alo[4];
                const uint32_t off = SWZ((uint32_t)(
                    (wm0 + mt * 16 + (lane & 15)) * 128 + ks * 32 + (lane >> 4) * 16));
                ldm_x4(ahi, base + off);
                ldm_x4(alo, base + TILE_B + off);
                #pragma unroll
                for (int nt = 0; nt < 4; nt++) {
                    const uint32_t* bh = &bhi[nt >> 1][(nt & 1) * 2];
                    const uint32_t* bl = &blo[nt >> 1][(nt & 1) * 2];
                    mma_bf16(acc[mt][nt], ahi, bh);
                    mma_bf16(acc[mt][nt], ahi, bl);
                    mma_bf16(acc[mt][nt], alo, bh);
                }
            }
        }
        __syncthreads();
    }

    // epilogue
    const int r0 = lane >> 2, cp2 = (lane & 3) * 2;
    #pragma unroll
    for (int mt = 0; mt < 4; mt++) {
        #pragma unroll
        for (int half = 0; half < 2; half++) {
            const int gm = m0 + wm0 + mt * 16 + r0 + half * 8;
            const float bm = (bias_mode == 1) ? bias[gm] : 0.f;
            #pragma unroll
            for (int nt = 0; nt < 4; nt++) {
                const int gn = n0 + wn0 + nt * 8 + cp2;
                float v0 = acc[mt][nt][half * 2 + 0] * scale + bm;
                float v1 = acc[mt][nt][half * 2 + 1] * scale + bm;
                if (bias_mode == 2) { v0 += bias[gn]; v1 += bias[gn + 1]; }
                const size_t idx = (size_t)bz * sC + (size_t)gm * ldc + gn;
                if (Cf) {
                    if (resid) {
                        const float* rp = resid + (size_t)bz * sR + (size_t)gm * ldc + gn;
                        v0 += rp[0]; v1 += rp[1];
                    }
                    float2 o = { v0, v1 };
                    *reinterpret_cast<float2*>(Cf + idx) = o;
                } else {
                    bf16 h0 = __float2bfloat16(v0), h1 = __float2bfloat16(v1);
                    bf162 hv = __halves2bfloat162(h0, h1);
                    bf162 lv = __halves2bfloat162(__float2bfloat16(v0 - __bfloat162float(h0)),
                                                  __float2bfloat16(v1 - __bfloat162float(h1)));
                    *reinterpret_cast<bf162*>(Chi + idx) = hv;
                    *reinterpret_cast<bf162*>(Clo + idx) = lv;
                }
            }
        }
    }
}

// ---------------- launch ----------------
#define SYM(p, s) do { void* _t = nullptr; cudaGetSymbolAddress(&_t, s); p = (decltype(p))_t; } while (0)

extern "C" void kernel_launch(void* const* d_in, const int* in_sizes, int n_in,
                              void* d_out, int out_size) {
    const float* x     = (const float*)d_in[0];
    const float* gamma = (const float*)d_in[1];
    const float* beta  = (const float*)d_in[2];
    const float* wq = (const float*)d_in[3];
    const float* bq = (const float*)d_in[4];
    const float* wk = (const float*)d_in[5];
    const float* bk = (const float*)d_in[6];
    const float* wv = (const float*)d_in[7];
    const float* bv = (const float*)d_in[8];
    const float* wo = (const float*)d_in[9];
    const float* bo = (const float*)d_in[10];
    float* out = (float*)d_out;

    bf16 *ht_h, *ht_l, *qt_h, *qt_l, *kt_h, *kt_l, *v_h, *v_l, *ot_h, *ot_l;
    bf16 *wq_h, *wq_l, *wk_h, *wk_l, *wv_h, *wv_l, *wo_h, *wo_l, *p_h, *p_l;
    float* s_ptr;
    SYM(ht_h, g_ht_hi); SYM(ht_l, g_ht_lo);
    SYM(qt_h, g_qt_hi); SYM(qt_l, g_qt_lo);
    SYM(kt_h, g_kt_hi); SYM(kt_l, g_kt_lo);
    SYM(v_h, g_v_hi);   SYM(v_l, g_v_lo);
    SYM(ot_h, g_ot_hi); SYM(ot_l, g_ot_lo);
    SYM(wq_h, g_wq_hi); SYM(wq_l, g_wq_lo);
    SYM(wk_h, g_wk_hi); SYM(wk_l, g_wk_lo);
    SYM(wv_h, g_wv_hi); SYM(wv_l, g_wv_lo);
    SYM(wo_h, g_wo_hi); SYM(wo_l, g_wo_lo);
    SYM(p_h, g_p_hi);   SYM(p_l, g_p_lo);
    SYM(s_ptr, g_s);

    cudaFuncSetAttribute(mma_gemm, cudaFuncAttributeMaxDynamicSharedMemorySize, SMEM_TOTAL);

    const int W4 = (CC * CC) / 4;
    decomp_kernel<<<(W4 + 255) / 256, 256>>>(wq, wq_h, wq_l, W4);
    decomp_kernel<<<(W4 + 255) / 256, 256>>>(wk, wk_h, wk_l, W4);
    decomp_kernel<<<(W4 + 255) / 256, 256>>>(wv, wv_h, wv_l, W4);
    decomp_kernel<<<(W4 + 255) / 256, 256>>>(wo, wo_h, wo_l, W4);

    gn_kernel<<<BB * NGROUPS, 256>>>(x, gamma, beta);

    const size_t sNC = (size_t)NN * CC, sCN = (size_t)CC * NN, sSS = (size_t)NN * NN;

    // Q^T[n,co] = h^T . Wq^T   (M=n, N=co)
    mma_gemm<<<dim3(4, 32, BB), 256, SMEM_TOTAL>>>(ht_h, ht_l, wq_h, wq_l, CC, CC, CC,
        sNC, 0, nullptr, qt_h, qt_l, CC, sNC, bq, 2, nullptr, 0, 1.f);
    mma_gemm<<<dim3(4, 32, BB), 256, SMEM_TOTAL>>>(ht_h, ht_l, wk_h, wk_l, CC, CC, CC,
        sNC, 0, nullptr, kt_h, kt_l, CC, sNC, bk, 2, nullptr, 0, 1.f);
    // V[co,n] = Wv . h        (M=co, N=n)
    mma_gemm<<<dim3(32, 4, BB), 256, SMEM_TOTAL>>>(wv_h, wv_l, ht_h, ht_l, CC, CC, CC,
        0, sNC, nullptr, v_h, v_l, NN, sCN, bv, 1, nullptr, 0, 1.f);
    // S[i,j] = scale * q^T . k   (M=N=4096)
    mma_gemm<<<dim3(32, 32, BB), 256, SMEM_TOTAL>>>(qt_h, qt_l, kt_h, kt_l, CC, CC, CC,
        sNC, sNC, s_ptr, nullptr, nullptr, NN, sSS, nullptr, 0, nullptr, 0,
        0.044194173824159216f);

    softmax_kernel<<<BB * NN, 256>>>();

    // O^T[i,c] = P . V^T      (M=i, N=c, K=j)
    mma_gemm<<<dim3(4, 32, BB), 256, SMEM_TOTAL>>>(p_h, p_l, v_h, v_l, NN, NN, NN,
        sSS, sCN, nullptr, ot_h, ot_l, CC, sNC, nullptr, 0, nullptr, 0, 1.f);
    // out[co,n] = Wo . o + bo + x
    mma_gemm<<<dim3(32, 4, BB), 256, SMEM_TOTAL>>>(wo_h, wo_l, ot_h, ot_l, CC, CC, CC,
        0, sNC, out, nullptr, nullptr, NN, sCN, bo, 1, x, sCN, 1.f);
}

// round 6
// speedup vs baseline: 3.1028x; 1.0157x over previous
#include <cuda_runtime.h>
#include <cuda_bf16.h>
#include <cstdint>
#include <math.h>

#define BB 2
#define CC 512
#define NN 4096
#define NGROUPS 32
#define CPG 16
#define EPS 1e-6f

typedef __nv_bfloat16 bf16;
typedef __nv_bfloat162 bf162;

// ---------------- scratch globals ----------------
__device__ bf16 g_ht_hi[(size_t)BB * NN * CC], g_ht_lo[(size_t)BB * NN * CC];   // h^T [b][n][c]
__device__ bf16 g_qt_hi[(size_t)BB * NN * CC], g_qt_lo[(size_t)BB * NN * CC];   // q^T [b][n][c]
__device__ bf16 g_kt_hi[(size_t)BB * NN * CC], g_kt_lo[(size_t)BB * NN * CC];
__device__ bf16 g_v_hi [(size_t)BB * CC * NN], g_v_lo [(size_t)BB * CC * NN];   // v [b][c][n]
__device__ bf16 g_ot_hi[(size_t)BB * NN * CC], g_ot_lo[(size_t)BB * NN * CC];   // o^T [b][n][c]
__device__ bf16 g_wq_hi[CC * CC], g_wq_lo[CC * CC];
__device__ bf16 g_wk_hi[CC * CC], g_wk_lo[CC * CC];
__device__ bf16 g_wv_hi[CC * CC], g_wv_lo[CC * CC];
__device__ bf16 g_wo_hi[CC * CC], g_wo_lo[CC * CC];
__device__ float g_s[(size_t)BB * NN * NN];                                      // logits
__device__ bf16 g_p_hi[(size_t)BB * NN * NN], g_p_lo[(size_t)BB * NN * NN];     // probs

// ---------------- PTX helpers ----------------
__device__ __forceinline__ uint32_t smem_u32(const void* p) {
    uint32_t a;
    asm("{ .reg .u64 t; cvta.to.shared.u64 t, %1; cvt.u32.u64 %0, t; }" : "=r"(a) : "l"(p));
    return a;
}
__device__ __forceinline__ void cp16(uint32_t saddr, const void* g) {
    asm volatile("cp.async.cg.shared.global [%0], [%1], 16;" :: "r"(saddr), "l"(g) : "memory");
}
#define CP_COMMIT() asm volatile("cp.async.commit_group;" ::: "memory")
#define CP_WAIT(n)  asm volatile("cp.async.wait_group %0;" :: "n"(n) : "memory")

__device__ __forceinline__ void ldm_x4(uint32_t* r, uint32_t addr) {
    asm volatile("ldmatrix.sync.aligned.m8n8.x4.shared.b16 {%0,%1,%2,%3}, [%4];"
        : "=r"(r[0]), "=r"(r[1]), "=r"(r[2]), "=r"(r[3]) : "r"(addr));
}
__device__ __forceinline__ void mma_bf16(float* d, const uint32_t* a, const uint32_t* b) {
    asm volatile("mma.sync.aligned.m16n8k16.row.col.f32.bf16.bf16.f32 "
        "{%0,%1,%2,%3}, {%4,%5,%6,%7}, {%8,%9}, {%0,%1,%2,%3};"
        : "+f"(d[0]), "+f"(d[1]), "+f"(d[2]), "+f"(d[3])
        : "r"(a[0]), "r"(a[1]), "r"(a[2]), "r"(a[3]), "r"(b[0]), "r"(b[1]));
}
#define SWZ(o) ((o) ^ (((o) >> 3) & 0x70))

// ---------------- GroupNorm -> h^T hi/lo ----------------
__global__ void gn_kernel(const float* __restrict__ x,
                          const float* __restrict__ gamma,
                          const float* __restrict__ beta) {
    __shared__ float tile[16][257];
    __shared__ float red[8], red2[8];
    __shared__ float sga[16], sbe[16], s_mean, s_rstd;
    const int bg = blockIdx.x, b = bg >> 5, g = bg & 31;
    const size_t xbase = ((size_t)b * CC + (size_t)g * CPG) * NN;
    const float* xp = x + xbase;
    const int tid = threadIdx.x;
    if (tid < 16) { sga[tid] = gamma[g * CPG + tid]; sbe[tid] = beta[g * CPG + tid]; }

    float s = 0.f, ss = 0.f;
    for (int i = tid * 4; i < CPG * NN; i += 1024) {
        float4 v = *reinterpret_cast<const float4*>(xp + i);
        s += v.x + v.y + v.z + v.w;
        ss += v.x * v.x + v.y * v.y + v.z * v.z + v.w * v.w;
    }
    #pragma unroll
    for (int o = 16; o; o >>= 1) {
        s += __shfl_xor_sync(0xffffffffu, s, o);
        ss += __shfl_xor_sync(0xffffffffu, ss, o);
    }
    if ((tid & 31) == 0) { red[tid >> 5] = s; red2[tid >> 5] = ss; }
    __syncthreads();
    if (tid == 0) {
        float S = 0.f, SS = 0.f;
        for (int i = 0; i < 8; i++) { S += red[i]; SS += red2[i]; }
        float mean = S / (float)(CPG * NN);
        s_mean = mean;
        s_rstd = rsqrtf(SS / (float)(CPG * NN) - mean * mean + EPS);
    }
    __syncthreads();
    const float mean = s_mean, rstd = s_rstd;

    for (int n0 = 0; n0 < NN; n0 += 256) {
        __syncthreads();
        for (int i = tid; i < 16 * 256; i += 256) {
            int c = i >> 8, n = i & 255;
            tile[c][n] = xp[(size_t)c * NN + n0 + n];
        }
        __syncthreads();
        const int n = n0 + tid;
        __align__(16) bf162 hv[8], lv[8];
        #pragma unroll
        for (int c2 = 0; c2 < 8; c2++) {
            float v0 = (tile[2 * c2][tid] - mean) * rstd * sga[2 * c2] + sbe[2 * c2];
            float v1 = (tile[2 * c2 + 1][tid] - mean) * rstd * sga[2 * c2 + 1] + sbe[2 * c2 + 1];
            bf16 h0 = __float2bfloat16(v0), h1 = __float2bfloat16(v1);
            hv[c2] = __halves2bfloat162(h0, h1);
            lv[c2] = __halves2bfloat162(__float2bfloat16(v0 - __bfloat162float(h0)),
                                        __float2bfloat16(v1 - __bfloat162float(h1)));
        }
        const size_t dst = ((size_t)b * NN + n) * CC + (size_t)g * CPG;
        *reinterpret_cast<uint4*>(g_ht_hi + dst)     = reinterpret_cast<uint4*>(hv)[0];
        *reinterpret_cast<uint4*>(g_ht_hi + dst + 8) = reinterpret_cast<uint4*>(hv)[1];
        *reinterpret_cast<uint4*>(g_ht_lo + dst)     = reinterpret_cast<uint4*>(lv)[0];
        *reinterpret_cast<uint4*>(g_ht_lo + dst + 8) = reinterpret_cast<uint4*>(lv)[1];
    }
}

// ---------------- fused weight hi/lo decomposition (4 weights in one) -------
__global__ void decomp4_kernel(const float* __restrict__ w0, const float* __restrict__ w1,
                               const float* __restrict__ w2, const float* __restrict__ w3) {
    const int wsel = blockIdx.y;
    const float* src = (wsel == 0) ? w0 : (wsel == 1) ? w1 : (wsel == 2) ? w2 : w3;
    bf16* hi = (wsel == 0) ? g_wq_hi : (wsel == 1) ? g_wk_hi : (wsel == 2) ? g_wv_hi : g_wo_hi;
    bf16* lo = (wsel == 0) ? g_wq_lo : (wsel == 1) ? g_wk_lo : (wsel == 2) ? g_wv_lo : g_wo_lo;
    int i = blockIdx.x * blockDim.x + threadIdx.x;
    if (i >= (CC * CC) / 4) return;
    float4 v = reinterpret_cast<const float4*>(src)[i];
    bf16 h0 = __float2bfloat16(v.x), h1 = __float2bfloat16(v.y);
    bf16 h2 = __float2bfloat16(v.z), h3 = __float2bfloat16(v.w);
    __align__(8) bf162 hv[2] = { __halves2bfloat162(h0, h1), __halves2bfloat162(h2, h3) };
    __align__(8) bf162 lv[2] = {
        __halves2bfloat162(__float2bfloat16(v.x - __bfloat162float(h0)),
                           __float2bfloat16(v.y - __bfloat162float(h1))),
        __halves2bfloat162(__float2bfloat16(v.z - __bfloat162float(h2)),
                           __float2bfloat16(v.w - __bfloat162float(h3))) };
    *reinterpret_cast<uint2*>(hi + 4 * (size_t)i) = *reinterpret_cast<uint2*>(hv);
    *reinterpret_cast<uint2*>(lo + 4 * (size_t)i) = *reinterpret_cast<uint2*>(lv);
}

// ---------------- softmax: fp32 logits -> bf16 hi/lo probs ----------------
__global__ void softmax_kernel() {
    __shared__ float row[NN];
    __shared__ float red[8];
    __shared__ float s_bcast;
    const size_t rbase = (size_t)blockIdx.x * NN;
    const float* sp = g_s + rbase;
    const int tid = threadIdx.x;

    float mx = -1e30f;
    for (int i = tid * 4; i < NN; i += 1024) {
        float4 v = *reinterpret_cast<const float4*>(sp + i);
        *reinterpret_cast<float4*>(row + i) = v;
        mx = fmaxf(fmaxf(v.x, v.y), fmaxf(fmaxf(v.z, v.w), mx));
    }
    #pragma unroll
    for (int o = 16; o; o >>= 1) mx = fmaxf(mx, __shfl_xor_sync(0xffffffffu, mx, o));
    if ((tid & 31) == 0) red[tid >> 5] = mx;
    __syncthreads();
    if (tid == 0) {
        float m = red[0];
        for (int i = 1; i < 8; i++) m = fmaxf(m, red[i]);
        s_bcast = m;
    }
    __syncthreads();
    mx = s_bcast;
    __syncthreads();

    float s = 0.f;
    for (int i = tid * 4; i < NN; i += 1024) {
        float4 v = *reinterpret_cast<float4*>(row + i);
        v.x = __expf(v.x - mx); v.y = __expf(v.y - mx);
        v.z = __expf(v.z - mx); v.w = __expf(v.w - mx);
        *reinterpret_cast<float4*>(row + i) = v;
        s += v.x + v.y + v.z + v.w;
    }
    #pragma unroll
    for (int o = 16; o; o >>= 1) s += __shfl_xor_sync(0xffffffffu, s, o);
    if ((tid & 31) == 0) red[tid >> 5] = s;
    __syncthreads();
    if (tid == 0) {
        float S = 0.f;
        for (int i = 0; i < 8; i++) S += red[i];
        s_bcast = 1.0f / S;
    }
    __syncthreads();
    const float inv = s_bcast;

    for (int i = tid * 4; i < NN; i += 1024) {
        float4 v = *reinterpret_cast<float4*>(row + i);
        float p0 = v.x * inv, p1 = v.y * inv, p2 = v.z * inv, p3 = v.w * inv;
        bf16 h0 = __float2bfloat16(p0), h1 = __float2bfloat16(p1);
        bf16 h2 = __float2bfloat16(p2), h3 = __float2bfloat16(p3);
        __align__(8) bf162 hv[2] = { __halves2bfloat162(h0, h1), __halves2bfloat162(h2, h3) };
        __align__(8) bf162 lv[2] = {
            __halves2bfloat162(__float2bfloat16(p0 - __bfloat162float(h0)),
                               __float2bfloat16(p1 - __bfloat162float(h1))),
            __halves2bfloat162(__float2bfloat16(p2 - __bfloat162float(h2)),
                               __float2bfloat16(p3 - __bfloat162float(h3))) };
        *reinterpret_cast<uint2*>(g_p_hi + rbase + i) = *reinterpret_cast<uint2*>(hv);
        *reinterpret_cast<uint2*>(g_p_lo + rbase + i) = *reinterpret_cast<uint2*>(lv);
    }
}

// ---------------- HMMA bf16x3 GEMM core (3-stage cp.async pipeline) --------
#define TILE_B 16384                      // one 128x64 bf16 tile (128B rows, SW128)
#define STAGE_B (4 * TILE_B)              // Ahi, Alo, Bhi, Blo
#define NSTAGE 3
#define SMEM_TOTAL (NSTAGE * STAGE_B)     // 196608

__device__ __forceinline__ void load_tile_async(const bf16* __restrict__ src, int row0,
                                                int ld, int k0, uint32_t sdst, int tid) {
    #pragma unroll
    for (int i = 0; i < 4; i++) {
        int c = tid + i * 256;                  // 0..1023 16B chunks
        int r = c >> 3, ck = c & 7;
        cp16(sdst + SWZ((uint32_t)(r * 128 + ck * 16)),
             src + (size_t)(row0 + r) * ld + k0 + ck * 8);
    }
}

__device__ __forceinline__ void gemm_core(
        const bf16* __restrict__ pAh, const bf16* __restrict__ pAl,
        const bf16* __restrict__ pBh, const bf16* __restrict__ pBl,
        int lda, int ldb, int K, int m0, int n0,
        float* __restrict__ Cf, bf16* __restrict__ Chi, bf16* __restrict__ Clo,
        int ldc, const float* __restrict__ bias, int bias_mode,
        const float* __restrict__ resid, float scale, char* smem) {
    const uint32_t sb = smem_u32(smem);
    const int tid = threadIdx.x, wid = tid >> 5, lane = tid & 31;
    const int wm0 = (wid & 1) * 64, wn0 = (wid >> 1) * 32;
    const int NC = K >> 6;
    float acc[4][4][4] = {};

    // prologue: stages 0,1
    load_tile_async(pAh, m0, lda, 0, sb, tid);
    load_tile_async(pAl, m0, lda, 0, sb + TILE_B, tid);
    load_tile_async(pBh, n0, ldb, 0, sb + 2 * TILE_B, tid);
    load_tile_async(pBl, n0, ldb, 0, sb + 3 * TILE_B, tid);
    CP_COMMIT();
    if (NC > 1) {
        load_tile_async(pAh, m0, lda, 64, sb + STAGE_B, tid);
        load_tile_async(pAl, m0, lda, 64, sb + STAGE_B + TILE_B, tid);
        load_tile_async(pBh, n0, ldb, 64, sb + STAGE_B + 2 * TILE_B, tid);
        load_tile_async(pBl, n0, ldb, 64, sb + STAGE_B + 3 * TILE_B, tid);
        CP_COMMIT();
    }

    int st = 0;
    for (int c = 0; c < NC; c++) {
        if (c + 1 < NC) { CP_WAIT(1); } else { CP_WAIT(0); }
        __syncthreads();
        if (c + 2 < NC) {
            int st2 = st + 2; if (st2 >= NSTAGE) st2 -= NSTAGE;
            uint32_t base = sb + st2 * STAGE_B;
            const int k0 = (c + 2) << 6;
            load_tile_async(pAh, m0, lda, k0, base, tid);
            load_tile_async(pAl, m0, lda, k0, base + TILE_B, tid);
            load_tile_async(pBh, n0, ldb, k0, base + 2 * TILE_B, tid);
            load_tile_async(pBl, n0, ldb, k0, base + 3 * TILE_B, tid);
            CP_COMMIT();
        }

        const uint32_t base = sb + st * STAGE_B;
        #pragma unroll
        for (int ks = 0; ks < 4; ks++) {
            uint32_t bhi[2][4], blo[2][4];
            #pragma unroll
            for (int nt2 = 0; nt2 < 2; nt2++) {
                const uint32_t off = SWZ((uint32_t)(
                    (wn0 + nt2 * 16 + ((lane >> 4) & 1) * 8 + (lane & 7)) * 128 +
                    ks * 32 + ((lane >> 3) & 1) * 16));
                ldm_x4(bhi[nt2], base + 2 * TILE_B + off);
                ldm_x4(blo[nt2], base + 3 * TILE_B + off);
            }
            #pragma unroll
            for (int mt = 0; mt < 4; mt++) {
                uint32_t ahi[4], alo[4];
                const uint32_t off = SWZ((uint32_t)(
                    (wm0 + mt * 16 + (lane & 15)) * 128 + ks * 32 + (lane >> 4) * 16));
                ldm_x4(ahi, base + off);
                ldm_x4(alo, base + TILE_B + off);
                #pragma unroll
                for (int nt = 0; nt < 4; nt++) {
                    const uint32_t* bh = &bhi[nt >> 1][(nt & 1) * 2];
                    const uint32_t* bl = &blo[nt >> 1][(nt & 1) * 2];
                    mma_bf16(acc[mt][nt], ahi, bh);
                    mma_bf16(acc[mt][nt], ahi, bl);
                    mma_bf16(acc[mt][nt], alo, bh);
                }
            }
        }
        st++; if (st >= NSTAGE) st = 0;
    }

    // epilogue
    const int r0 = lane >> 2, cp2 = (lane & 3) * 2;
    #pragma unroll
    for (int mt = 0; mt < 4; mt++) {
        #pragma unroll
        for (int half = 0; half < 2; half++) {
            const int gm = m0 + wm0 + mt * 16 + r0 + half * 8;
            const float bm = (bias_mode == 1) ? bias[gm] : 0.f;
            #pragma unroll
            for (int nt = 0; nt < 4; nt++) {
                const int gn = n0 + wn0 + nt * 8 + cp2;
                float v0 = acc[mt][nt][half * 2 + 0] * scale + bm;
                float v1 = acc[mt][nt][half * 2 + 1] * scale + bm;
                if (bias_mode == 2) { v0 += bias[gn]; v1 += bias[gn + 1]; }
                const size_t idx = (size_t)gm * ldc + gn;
                if (Cf) {
                    if (resid) { v0 += resid[idx]; v1 += resid[idx + 1]; }
                    float2 o = { v0, v1 };
                    *reinterpret_cast<float2*>(Cf + idx) = o;
                } else {
                    bf16 h0 = __float2bfloat16(v0), h1 = __float2bfloat16(v1);
                    bf162 hv = __halves2bfloat162(h0, h1);
                    bf162 lv = __halves2bfloat162(__float2bfloat16(v0 - __bfloat162float(h0)),
                                                  __float2bfloat16(v1 - __bfloat162float(h1)));
                    *reinterpret_cast<bf162*>(Chi + idx) = hv;
                    *reinterpret_cast<bf162*>(Clo + idx) = lv;
                }
            }
        }
    }
}

// Generic wrapper (S, O, final)
__global__ void __launch_bounds__(256, 1)
mma_gemm(const bf16* __restrict__ Ah, const bf16* __restrict__ Al,
         const bf16* __restrict__ Bh, const bf16* __restrict__ Bl,
         int lda, int ldb, int K, size_t sA, size_t sB,
         float* __restrict__ Cf, bf16* __restrict__ Chi, bf16* __restrict__ Clo,
         int ldc, size_t sC,
         const float* __restrict__ bias, int bias_mode,
         const float* __restrict__ resid, size_t sR, float scale) {
    extern __shared__ __align__(1024) char smem[];
    const int bz = blockIdx.z;
    gemm_core(Ah + (size_t)bz * sA, Al + (size_t)bz * sA,
              Bh + (size_t)bz * sB, Bl + (size_t)bz * sB,
              lda, ldb, K, blockIdx.y * 128, blockIdx.x * 128,
              Cf ? Cf + (size_t)bz * sC : nullptr,
              Chi ? Chi + (size_t)bz * sC : nullptr,
              Clo ? Clo + (size_t)bz * sC : nullptr,
              ldc, bias, bias_mode,
              resid ? resid + (size_t)bz * sR : nullptr, scale, smem);
}

// Fused QKV wrapper: grid (4, 32, BB*3); z -> (batch, op)
__global__ void __launch_bounds__(256, 1)
qkv_gemm(const float* __restrict__ bq, const float* __restrict__ bk,
         const float* __restrict__ bv) {
    extern __shared__ __align__(1024) char smem[];
    const int z = blockIdx.z;
    const int b = z / 3, op = z - b * 3;
    const size_t sNC = (size_t)NN * CC, sCN = (size_t)CC * NN;
    const bf16* hth = g_ht_hi + (size_t)b * sNC;
    const bf16* htl = g_ht_lo + (size_t)b * sNC;
    if (op == 2) {
        // V[co,n] = Wv . h^T^T : A = Wv (M=co), B = h^T (N=n, K-major over c)
        gemm_core(g_wv_hi, g_wv_lo, hth, htl, CC, CC, CC,
                  blockIdx.x * 128, blockIdx.y * 128,
                  nullptr, g_v_hi + (size_t)b * sCN, g_v_lo + (size_t)b * sCN,
                  NN, bv, 1, nullptr, 1.f, smem);
    } else if (op == 0) {
        gemm_core(hth, htl, g_wq_hi, g_wq_lo, CC, CC, CC,
                  blockIdx.y * 128, blockIdx.x * 128,
                  nullptr, g_qt_hi + (size_t)b * sNC, g_qt_lo + (size_t)b * sNC,
                  CC, bq, 2, nullptr, 1.f, smem);
    } else {
        gemm_core(hth, htl, g_wk_hi, g_wk_lo, CC, CC, CC,
                  blockIdx.y * 128, blockIdx.x * 128,
                  nullptr, g_kt_hi + (size_t)b * sNC, g_kt_lo + (size_t)b * sNC,
                  CC, bk, 2, nullptr, 1.f, smem);
    }
}

// ---------------- launch ----------------
#define SYM(p, s) do { void* _t = nullptr; cudaGetSymbolAddress(&_t, s); p = (decltype(p))_t; } while (0)

extern "C" void kernel_launch(void* const* d_in, const int* in_sizes, int n_in,
                              void* d_out, int out_size) {
    const float* x     = (const float*)d_in[0];
    const float* gamma = (const float*)d_in[1];
    const float* beta  = (const float*)d_in[2];
    const float* wq = (const float*)d_in[3];
    const float* bq = (const float*)d_in[4];
    const float* wk = (const float*)d_in[5];
    const float* bk = (const float*)d_in[6];
    const float* wv = (const float*)d_in[7];
    const float* bv = (const float*)d_in[8];
    const float* wo = (const float*)d_in[9];
    const float* bo = (const float*)d_in[10];
    float* out = (float*)d_out;

    bf16 *qt_h, *qt_l, *kt_h, *kt_l, *v_h, *v_l, *ot_h, *ot_l;
    bf16 *wo_h, *wo_l, *p_h, *p_l;
    float* s_ptr;
    SYM(qt_h, g_qt_hi); SYM(qt_l, g_qt_lo);
    SYM(kt_h, g_kt_hi); SYM(kt_l, g_kt_lo);
    SYM(v_h, g_v_hi);   SYM(v_l, g_v_lo);
    SYM(ot_h, g_ot_hi); SYM(ot_l, g_ot_lo);
    SYM(wo_h, g_wo_hi); SYM(wo_l, g_wo_lo);
    SYM(p_h, g_p_hi);   SYM(p_l, g_p_lo);
    SYM(s_ptr, g_s);

    cudaFuncSetAttribute(mma_gemm, cudaFuncAttributeMaxDynamicSharedMemorySize, SMEM_TOTAL);
    cudaFuncSetAttribute(qkv_gemm, cudaFuncAttributeMaxDynamicSharedMemorySize, SMEM_TOTAL);

    decomp4_kernel<<<dim3((CC * CC / 4 + 255) / 256, 4), 256>>>(wq, wk, wv, wo);
    gn_kernel<<<BB * NGROUPS, 256>>>(x, gamma, beta);

    const size_t sNC = (size_t)NN * CC, sCN = (size_t)CC * NN, sSS = (size_t)NN * NN;

    // fused Q^T, K^T, V
    qkv_gemm<<<dim3(4, 32, BB * 3), 256, SMEM_TOTAL>>>(bq, bk, bv);

    // S[i,j] = scale * q^T . k
    mma_gemm<<<dim3(32, 32, BB), 256, SMEM_TOTAL>>>(qt_h, qt_l, kt_h, kt_l, CC, CC, CC,
        sNC, sNC, s_ptr, nullptr, nullptr, NN, sSS, nullptr, 0, nullptr, 0,
        0.044194173824159216f);

    softmax_kernel<<<BB * NN, 256>>>();

    // O^T[i,c] = P . V^T
    mma_gemm<<<dim3(4, 32, BB), 256, SMEM_TOTAL>>>(p_h, p_l, v_h, v_l, NN, NN, NN,
        sSS, sCN, nullptr, ot_h, ot_l, CC, sNC, nullptr, 0, nullptr, 0, 1.f);
    // out[co,n] = Wo . o + bo + x
    mma_gemm<<<dim3(32, 4, BB), 256, SMEM_TOTAL>>>(wo_h, wo_l, ot_h, ot_l, CC, CC, CC,
        0, sNC, out, nullptr, nullptr, NN, sCN, bo, 1, x, sCN, 1.f);
}